// round 6
// baseline (speedup 1.0000x reference)
#include <cuda_runtime.h>

// SDPA: out = softmax(Q K^T / sqrt(D) + mask) V
// B=1, H=16, S=4096, D=64, all fp32. mask is [1,1,S,S] (head-independent).
//
// Round-0 baseline: numerically safe fp32 SIMT flash attention.
// One CTA = (head, 64-row Q tile). 256 threads as 16x16 (ty x tx).
// Smem: 3 x 16KB tiles, XOR-swizzled at float4 granularity for conflict-free
// LDS.128 on both the store and load patterns. K-tile region is reused to
// hold the P (probability) tile between the two GEMMs.

static constexpr int Hn = 16;
static constexpr int Sn = 4096;
static constexpr int Dn = 64;
static constexpr int BQ = 64;
static constexpr int BK = 64;

__global__ void __launch_bounds__(256)
sdpa_fp32_kernel(const float* __restrict__ Q,
                 const float* __restrict__ K,
                 const float* __restrict__ V,
                 const float* __restrict__ M,
                 float* __restrict__ O)
{
    // float4-granular tiles: [row][16 float4 units], unit index swizzled by row.
    __shared__ float4 q_sm[BQ * 16];
    __shared__ float4 kp_sm[BK * 16];   // K tile, then reused as P tile
    __shared__ float4 v_sm[BK * 16];

    const int tid = threadIdx.x;
    const int tx  = tid & 15;   // column-group lane
    const int ty  = tid >> 4;   // row-group lane
    const int q0  = blockIdx.x * BQ;
    const int h   = blockIdx.y;

    const float* __restrict__ Qh = Q + (size_t)h * Sn * Dn;
    const float* __restrict__ Kh = K + (size_t)h * Sn * Dn;
    const float* __restrict__ Vh = V + (size_t)h * Sn * Dn;

    // ---- Load Q tile (pre-scaled by 1/sqrt(D) = 0.125, exact in fp32) ----
    for (int i = tid; i < BQ * 16; i += 256) {
        const int row = i >> 4;
        const int d4  = i & 15;
        float4 qv = *reinterpret_cast<const float4*>(Qh + (q0 + row) * Dn + d4 * 4);
        qv.x *= 0.125f; qv.y *= 0.125f; qv.z *= 0.125f; qv.w *= 0.125f;
        q_sm[row * 16 + (d4 ^ (row & 15))] = qv;
    }

    // Per-thread state. Rows owned: r = ty + 16*jr (replicated across tx lanes
    // for m/l; O columns owned: dd = 4*tx + k).
    float o[4][4];
    float m_run[4], l_run[4];
    #pragma unroll
    for (int jr = 0; jr < 4; ++jr) {
        m_run[jr] = -1e30f;
        l_run[jr] = 0.0f;
        #pragma unroll
        for (int k = 0; k < 4; ++k) o[jr][k] = 0.0f;
    }

    for (int kt = 0; kt < Sn / BK; ++kt) {
        __syncthreads();   // previous iteration's PV reads of kp_sm/v_sm done

        // ---- Load K and V tiles (coalesced global, swizzled smem store) ----
        {
            const float* Kt = Kh + kt * BK * Dn;
            const float* Vt = Vh + kt * BK * Dn;
            for (int i = tid; i < BK * 16; i += 256) {
                const int row = i >> 4;
                const int d4  = i & 15;
                const int sw  = row * 16 + (d4 ^ (row & 15));
                kp_sm[sw] = *reinterpret_cast<const float4*>(Kt + row * Dn + d4 * 4);
                v_sm[sw]  = *reinterpret_cast<const float4*>(Vt + row * Dn + d4 * 4);
            }
        }
        __syncthreads();

        // ---- S = Qs K^T  (scores; thread tile rows r=ty+16jr, cols c=tx+16jc) ----
        float s[4][4];
        #pragma unroll
        for (int jr = 0; jr < 4; ++jr)
            #pragma unroll
            for (int jc = 0; jc < 4; ++jc) s[jr][jc] = 0.0f;

        #pragma unroll 4
        for (int d4 = 0; d4 < 16; ++d4) {
            float4 a[4], b[4];
            #pragma unroll
            for (int j = 0; j < 4; ++j) {
                const int r = ty + 16 * j;
                a[j] = q_sm[r * 16 + (d4 ^ (r & 15))];    // broadcast within half-warp
            }
            #pragma unroll
            for (int j = 0; j < 4; ++j) {
                const int c = tx + 16 * j;
                b[j] = kp_sm[c * 16 + (d4 ^ (c & 15))];   // conflict-free across tx
            }
            #pragma unroll
            for (int jr = 0; jr < 4; ++jr)
                #pragma unroll
                for (int jc = 0; jc < 4; ++jc) {
                    s[jr][jc] += a[jr].x * b[jc].x;
                    s[jr][jc] += a[jr].y * b[jc].y;
                    s[jr][jc] += a[jr].z * b[jc].z;
                    s[jr][jc] += a[jr].w * b[jc].w;
                }
        }

        // ---- additive mask (head-independent, coalesced across tx) ----
        #pragma unroll
        for (int jr = 0; jr < 4; ++jr) {
            const size_t mrow = (size_t)(q0 + ty + 16 * jr) * Sn + kt * BK;
            #pragma unroll
            for (int jc = 0; jc < 4; ++jc)
                s[jr][jc] += __ldg(M + mrow + tx + 16 * jc);
        }

        // ---- online softmax update (row reductions across the 16 tx lanes) ----
        float alpha[4];
        #pragma unroll
        for (int jr = 0; jr < 4; ++jr) {
            float rmax = s[jr][0];
            #pragma unroll
            for (int jc = 1; jc < 4; ++jc) rmax = fmaxf(rmax, s[jr][jc]);
            #pragma unroll
            for (int sh = 1; sh < 16; sh <<= 1)
                rmax = fmaxf(rmax, __shfl_xor_sync(0xffffffffu, rmax, sh));

            const float mnew = fmaxf(m_run[jr], rmax);
            alpha[jr] = __expf(m_run[jr] - mnew);
            m_run[jr] = mnew;

            float rsum = 0.0f;
            #pragma unroll
            for (int jc = 0; jc < 4; ++jc) {
                s[jr][jc] = __expf(s[jr][jc] - mnew);
                rsum += s[jr][jc];
            }
            #pragma unroll
            for (int sh = 1; sh < 16; sh <<= 1)
                rsum += __shfl_xor_sync(0xffffffffu, rsum, sh);

            l_run[jr] = l_run[jr] * alpha[jr] + rsum;
            #pragma unroll
            for (int k = 0; k < 4; ++k) o[jr][k] *= alpha[jr];
        }

        __syncthreads();   // done reading kp_sm as K

        // ---- write P tile into kp_sm (same float4-granular swizzle) ----
        {
            float* kp_w = reinterpret_cast<float*>(kp_sm);
            #pragma unroll
            for (int jr = 0; jr < 4; ++jr) {
                const int r = ty + 16 * jr;
                #pragma unroll
                for (int jc = 0; jc < 4; ++jc) {
                    const int c = tx + 16 * jc;
                    kp_w[r * 64 + ((((c >> 2) ^ (r & 15)) << 2) | (c & 3))] = s[jr][jc];
                }
            }
        }
        __syncthreads();

        // ---- O += P V  (thread tile rows r=ty+16jr, output dims dd=4tx..4tx+3) ----
        #pragma unroll 4
        for (int c4 = 0; c4 < 16; ++c4) {
            float4 a[4];
            #pragma unroll
            for (int jr = 0; jr < 4; ++jr) {
                const int r = ty + 16 * jr;
                a[jr] = kp_sm[r * 16 + (c4 ^ (r & 15))];   // P[r][4c4..4c4+3], broadcast
            }
            #pragma unroll
            for (int cc = 0; cc < 4; ++cc) {
                const int c = c4 * 4 + cc;
                const float4 b = v_sm[c * 16 + (tx ^ (c & 15))];   // V[c][4tx..4tx+3]
                #pragma unroll
                for (int jr = 0; jr < 4; ++jr) {
                    const float pa = (cc == 0) ? a[jr].x
                                   : (cc == 1) ? a[jr].y
                                   : (cc == 2) ? a[jr].z
                                               : a[jr].w;
                    o[jr][0] += pa * b.x;
                    o[jr][1] += pa * b.y;
                    o[jr][2] += pa * b.z;
                    o[jr][3] += pa * b.w;
                }
            }
        }
    }

    // ---- epilogue: normalize and store (coalesced float4) ----
    #pragma unroll
    for (int jr = 0; jr < 4; ++jr) {
        const float inv = 1.0f / l_run[jr];
        float4 ov;
        ov.x = o[jr][0] * inv;
        ov.y = o[jr][1] * inv;
        ov.z = o[jr][2] * inv;
        ov.w = o[jr][3] * inv;
        *reinterpret_cast<float4*>(
            O + (size_t)(h * Sn + q0 + ty + 16 * jr) * Dn + tx * 4) = ov;
    }
}

extern "C" void kernel_launch(void* const* d_in, const int* in_sizes, int n_in,
                              void* d_out, int out_size)
{
    (void)in_sizes; (void)n_in; (void)out_size;
    const float* Qp = (const float*)d_in[0];
    const float* Kp = (const float*)d_in[1];
    const float* Vp = (const float*)d_in[2];
    const float* Mp = (const float*)d_in[3];
    float* Op = (float*)d_out;

    dim3 grid(Sn / BQ, Hn);
    sdpa_fp32_kernel<<<grid, 256>>>(Qp, Kp, Vp, Mp, Op);
}

// round 7
// speedup vs baseline: 1.0017x; 1.0017x over previous
#include <cuda_runtime.h>

// SDPA: out = softmax(Q K^T / sqrt(D) + mask) V
// B=1, H=16, S=4096, D=64, all fp32. mask is [1,1,S,S] (head-independent).
//
// Round-0 baseline: numerically safe fp32 SIMT flash attention.
// One CTA = (head, 64-row Q tile). 256 threads as 16x16 (ty x tx).
// Smem: 3 x 16KB tiles, XOR-swizzled at float4 granularity for conflict-free
// LDS.128 on both the store and load patterns. K-tile region is reused to
// hold the P (probability) tile between the two GEMMs.

static constexpr int Hn = 16;
static constexpr int Sn = 4096;
static constexpr int Dn = 64;
static constexpr int BQ = 64;
static constexpr int BK = 64;

__global__ void __launch_bounds__(256)
sdpa_fp32_kernel(const float* __restrict__ Q,
                 const float* __restrict__ K,
                 const float* __restrict__ V,
                 const float* __restrict__ M,
                 float* __restrict__ O)
{
    // float4-granular tiles: [row][16 float4 units], unit index swizzled by row.
    __shared__ float4 q_sm[BQ * 16];
    __shared__ float4 kp_sm[BK * 16];   // K tile, then reused as P tile
    __shared__ float4 v_sm[BK * 16];

    const int tid = threadIdx.x;
    const int tx  = tid & 15;   // column-group lane
    const int ty  = tid >> 4;   // row-group lane
    const int q0  = blockIdx.x * BQ;
    const int h   = blockIdx.y;

    const float* __restrict__ Qh = Q + (size_t)h * Sn * Dn;
    const float* __restrict__ Kh = K + (size_t)h * Sn * Dn;
    const float* __restrict__ Vh = V + (size_t)h * Sn * Dn;

    // ---- Load Q tile (pre-scaled by 1/sqrt(D) = 0.125, exact in fp32) ----
    for (int i = tid; i < BQ * 16; i += 256) {
        const int row = i >> 4;
        const int d4  = i & 15;
        float4 qv = *reinterpret_cast<const float4*>(Qh + (q0 + row) * Dn + d4 * 4);
        qv.x *= 0.125f; qv.y *= 0.125f; qv.z *= 0.125f; qv.w *= 0.125f;
        q_sm[row * 16 + (d4 ^ (row & 15))] = qv;
    }

    // Per-thread state. Rows owned: r = ty + 16*jr (replicated across tx lanes
    // for m/l; O columns owned: dd = 4*tx + k).
    float o[4][4];
    float m_run[4], l_run[4];
    #pragma unroll
    for (int jr = 0; jr < 4; ++jr) {
        m_run[jr] = -1e30f;
        l_run[jr] = 0.0f;
        #pragma unroll
        for (int k = 0; k < 4; ++k) o[jr][k] = 0.0f;
    }

    for (int kt = 0; kt < Sn / BK; ++kt) {
        __syncthreads();   // previous iteration's PV reads of kp_sm/v_sm done

        // ---- Load K and V tiles (coalesced global, swizzled smem store) ----
        {
            const float* Kt = Kh + kt * BK * Dn;
            const float* Vt = Vh + kt * BK * Dn;
            for (int i = tid; i < BK * 16; i += 256) {
                const int row = i >> 4;
                const int d4  = i & 15;
                const int sw  = row * 16 + (d4 ^ (row & 15));
                kp_sm[sw] = *reinterpret_cast<const float4*>(Kt + row * Dn + d4 * 4);
                v_sm[sw]  = *reinterpret_cast<const float4*>(Vt + row * Dn + d4 * 4);
            }
        }
        __syncthreads();

        // ---- S = Qs K^T  (scores; thread tile rows r=ty+16jr, cols c=tx+16jc) ----
        float s[4][4];
        #pragma unroll
        for (int jr = 0; jr < 4; ++jr)
            #pragma unroll
            for (int jc = 0; jc < 4; ++jc) s[jr][jc] = 0.0f;

        #pragma unroll 4
        for (int d4 = 0; d4 < 16; ++d4) {
            float4 a[4], b[4];
            #pragma unroll
            for (int j = 0; j < 4; ++j) {
                const int r = ty + 16 * j;
                a[j] = q_sm[r * 16 + (d4 ^ (r & 15))];    // broadcast within half-warp
            }
            #pragma unroll
            for (int j = 0; j < 4; ++j) {
                const int c = tx + 16 * j;
                b[j] = kp_sm[c * 16 + (d4 ^ (c & 15))];   // conflict-free across tx
            }
            #pragma unroll
            for (int jr = 0; jr < 4; ++jr)
                #pragma unroll
                for (int jc = 0; jc < 4; ++jc) {
                    s[jr][jc] += a[jr].x * b[jc].x;
                    s[jr][jc] += a[jr].y * b[jc].y;
                    s[jr][jc] += a[jr].z * b[jc].z;
                    s[jr][jc] += a[jr].w * b[jc].w;
                }
        }

        // ---- additive mask (head-independent, coalesced across tx) ----
        #pragma unroll
        for (int jr = 0; jr < 4; ++jr) {
            const size_t mrow = (size_t)(q0 + ty + 16 * jr) * Sn + kt * BK;
            #pragma unroll
            for (int jc = 0; jc < 4; ++jc)
                s[jr][jc] += __ldg(M + mrow + tx + 16 * jc);
        }

        // ---- online softmax update (row reductions across the 16 tx lanes) ----
        float alpha[4];
        #pragma unroll
        for (int jr = 0; jr < 4; ++jr) {
            float rmax = s[jr][0];
            #pragma unroll
            for (int jc = 1; jc < 4; ++jc) rmax = fmaxf(rmax, s[jr][jc]);
            #pragma unroll
            for (int sh = 1; sh < 16; sh <<= 1)
                rmax = fmaxf(rmax, __shfl_xor_sync(0xffffffffu, rmax, sh));

            const float mnew = fmaxf(m_run[jr], rmax);
            alpha[jr] = __expf(m_run[jr] - mnew);
            m_run[jr] = mnew;

            float rsum = 0.0f;
            #pragma unroll
            for (int jc = 0; jc < 4; ++jc) {
                s[jr][jc] = __expf(s[jr][jc] - mnew);
                rsum += s[jr][jc];
            }
            #pragma unroll
            for (int sh = 1; sh < 16; sh <<= 1)
                rsum += __shfl_xor_sync(0xffffffffu, rsum, sh);

            l_run[jr] = l_run[jr] * alpha[jr] + rsum;
            #pragma unroll
            for (int k = 0; k < 4; ++k) o[jr][k] *= alpha[jr];
        }

        __syncthreads();   // done reading kp_sm as K

        // ---- write P tile into kp_sm (same float4-granular swizzle) ----
        {
            float* kp_w = reinterpret_cast<float*>(kp_sm);
            #pragma unroll
            for (int jr = 0; jr < 4; ++jr) {
                const int r = ty + 16 * jr;
                #pragma unroll
                for (int jc = 0; jc < 4; ++jc) {
                    const int c = tx + 16 * jc;
                    kp_w[r * 64 + ((((c >> 2) ^ (r & 15)) << 2) | (c & 3))] = s[jr][jc];
                }
            }
        }
        __syncthreads();

        // ---- O += P V  (thread tile rows r=ty+16jr, output dims dd=4tx..4tx+3) ----
        #pragma unroll 4
        for (int c4 = 0; c4 < 16; ++c4) {
            float4 a[4];
            #pragma unroll
            for (int jr = 0; jr < 4; ++jr) {
                const int r = ty + 16 * jr;
                a[jr] = kp_sm[r * 16 + (c4 ^ (r & 15))];   // P[r][4c4..4c4+3], broadcast
            }
            #pragma unroll
            for (int cc = 0; cc < 4; ++cc) {
                const int c = c4 * 4 + cc;
                const float4 b = v_sm[c * 16 + (tx ^ (c & 15))];   // V[c][4tx..4tx+3]
                #pragma unroll
                for (int jr = 0; jr < 4; ++jr) {
                    const float pa = (cc == 0) ? a[jr].x
                                   : (cc == 1) ? a[jr].y
                                   : (cc == 2) ? a[jr].z
                                               : a[jr].w;
                    o[jr][0] += pa * b.x;
                    o[jr][1] += pa * b.y;
                    o[jr][2] += pa * b.z;
                    o[jr][3] += pa * b.w;
                }
            }
        }
    }

    // ---- epilogue: normalize and store (coalesced float4) ----
    #pragma unroll
    for (int jr = 0; jr < 4; ++jr) {
        const float inv = 1.0f / l_run[jr];
        float4 ov;
        ov.x = o[jr][0] * inv;
        ov.y = o[jr][1] * inv;
        ov.z = o[jr][2] * inv;
        ov.w = o[jr][3] * inv;
        *reinterpret_cast<float4*>(
            O + (size_t)(h * Sn + q0 + ty + 16 * jr) * Dn + tx * 4) = ov;
    }
}

extern "C" void kernel_launch(void* const* d_in, const int* in_sizes, int n_in,
                              void* d_out, int out_size)
{
    (void)in_sizes; (void)n_in; (void)out_size;
    const float* Qp = (const float*)d_in[0];
    const float* Kp = (const float*)d_in[1];
    const float* Vp = (const float*)d_in[2];
    const float* Mp = (const float*)d_in[3];
    float* Op = (float*)d_out;

    dim3 grid(Sn / BQ, Hn);
    sdpa_fp32_kernel<<<grid, 256>>>(Qp, Kp, Vp, Mp, Op);
}

// round 8
// speedup vs baseline: 1.0086x; 1.0069x over previous
#include <cuda_runtime.h>

// SDPA: out = softmax(Q K^T / sqrt(D) + mask) V
// B=1, H=16, S=4096, D=64, all fp32. mask is [1,1,S,S] (head-independent).
//
// Round-0 baseline: numerically safe fp32 SIMT flash attention.
// One CTA = (head, 64-row Q tile). 256 threads as 16x16 (ty x tx).
// Smem: 3 x 16KB tiles, XOR-swizzled at float4 granularity for conflict-free
// LDS.128 on both the store and load patterns. K-tile region is reused to
// hold the P (probability) tile between the two GEMMs.

static constexpr int Hn = 16;
static constexpr int Sn = 4096;
static constexpr int Dn = 64;
static constexpr int BQ = 64;
static constexpr int BK = 64;

__global__ void __launch_bounds__(256)
sdpa_fp32_kernel(const float* __restrict__ Q,
                 const float* __restrict__ K,
                 const float* __restrict__ V,
                 const float* __restrict__ M,
                 float* __restrict__ O)
{
    // float4-granular tiles: [row][16 float4 units], unit index swizzled by row.
    __shared__ float4 q_sm[BQ * 16];
    __shared__ float4 kp_sm[BK * 16];   // K tile, then reused as P tile
    __shared__ float4 v_sm[BK * 16];

    const int tid = threadIdx.x;
    const int tx  = tid & 15;   // column-group lane
    const int ty  = tid >> 4;   // row-group lane
    const int q0  = blockIdx.x * BQ;
    const int h   = blockIdx.y;

    const float* __restrict__ Qh = Q + (size_t)h * Sn * Dn;
    const float* __restrict__ Kh = K + (size_t)h * Sn * Dn;
    const float* __restrict__ Vh = V + (size_t)h * Sn * Dn;

    // ---- Load Q tile (pre-scaled by 1/sqrt(D) = 0.125, exact in fp32) ----
    for (int i = tid; i < BQ * 16; i += 256) {
        const int row = i >> 4;
        const int d4  = i & 15;
        float4 qv = *reinterpret_cast<const float4*>(Qh + (q0 + row) * Dn + d4 * 4);
        qv.x *= 0.125f; qv.y *= 0.125f; qv.z *= 0.125f; qv.w *= 0.125f;
        q_sm[row * 16 + (d4 ^ (row & 15))] = qv;
    }

    // Per-thread state. Rows owned: r = ty + 16*jr (replicated across tx lanes
    // for m/l; O columns owned: dd = 4*tx + k).
    float o[4][4];
    float m_run[4], l_run[4];
    #pragma unroll
    for (int jr = 0; jr < 4; ++jr) {
        m_run[jr] = -1e30f;
        l_run[jr] = 0.0f;
        #pragma unroll
        for (int k = 0; k < 4; ++k) o[jr][k] = 0.0f;
    }

    for (int kt = 0; kt < Sn / BK; ++kt) {
        __syncthreads();   // previous iteration's PV reads of kp_sm/v_sm done

        // ---- Load K and V tiles (coalesced global, swizzled smem store) ----
        {
            const float* Kt = Kh + kt * BK * Dn;
            const float* Vt = Vh + kt * BK * Dn;
            for (int i = tid; i < BK * 16; i += 256) {
                const int row = i >> 4;
                const int d4  = i & 15;
                const int sw  = row * 16 + (d4 ^ (row & 15));
                kp_sm[sw] = *reinterpret_cast<const float4*>(Kt + row * Dn + d4 * 4);
                v_sm[sw]  = *reinterpret_cast<const float4*>(Vt + row * Dn + d4 * 4);
            }
        }
        __syncthreads();

        // ---- S = Qs K^T  (scores; thread tile rows r=ty+16jr, cols c=tx+16jc) ----
        float s[4][4];
        #pragma unroll
        for (int jr = 0; jr < 4; ++jr)
            #pragma unroll
            for (int jc = 0; jc < 4; ++jc) s[jr][jc] = 0.0f;

        #pragma unroll 4
        for (int d4 = 0; d4 < 16; ++d4) {
            float4 a[4], b[4];
            #pragma unroll
            for (int j = 0; j < 4; ++j) {
                const int r = ty + 16 * j;
                a[j] = q_sm[r * 16 + (d4 ^ (r & 15))];    // broadcast within half-warp
            }
            #pragma unroll
            for (int j = 0; j < 4; ++j) {
                const int c = tx + 16 * j;
                b[j] = kp_sm[c * 16 + (d4 ^ (c & 15))];   // conflict-free across tx
            }
            #pragma unroll
            for (int jr = 0; jr < 4; ++jr)
                #pragma unroll
                for (int jc = 0; jc < 4; ++jc) {
                    s[jr][jc] += a[jr].x * b[jc].x;
                    s[jr][jc] += a[jr].y * b[jc].y;
                    s[jr][jc] += a[jr].z * b[jc].z;
                    s[jr][jc] += a[jr].w * b[jc].w;
                }
        }

        // ---- additive mask (head-independent, coalesced across tx) ----
        #pragma unroll
        for (int jr = 0; jr < 4; ++jr) {
            const size_t mrow = (size_t)(q0 + ty + 16 * jr) * Sn + kt * BK;
            #pragma unroll
            for (int jc = 0; jc < 4; ++jc)
                s[jr][jc] += __ldg(M + mrow + tx + 16 * jc);
        }

        // ---- online softmax update (row reductions across the 16 tx lanes) ----
        float alpha[4];
        #pragma unroll
        for (int jr = 0; jr < 4; ++jr) {
            float rmax = s[jr][0];
            #pragma unroll
            for (int jc = 1; jc < 4; ++jc) rmax = fmaxf(rmax, s[jr][jc]);
            #pragma unroll
            for (int sh = 1; sh < 16; sh <<= 1)
                rmax = fmaxf(rmax, __shfl_xor_sync(0xffffffffu, rmax, sh));

            const float mnew = fmaxf(m_run[jr], rmax);
            alpha[jr] = __expf(m_run[jr] - mnew);
            m_run[jr] = mnew;

            float rsum = 0.0f;
            #pragma unroll
            for (int jc = 0; jc < 4; ++jc) {
                s[jr][jc] = __expf(s[jr][jc] - mnew);
                rsum += s[jr][jc];
            }
            #pragma unroll
            for (int sh = 1; sh < 16; sh <<= 1)
                rsum += __shfl_xor_sync(0xffffffffu, rsum, sh);

            l_run[jr] = l_run[jr] * alpha[jr] + rsum;
            #pragma unroll
            for (int k = 0; k < 4; ++k) o[jr][k] *= alpha[jr];
        }

        __syncthreads();   // done reading kp_sm as K

        // ---- write P tile into kp_sm (same float4-granular swizzle) ----
        {
            float* kp_w = reinterpret_cast<float*>(kp_sm);
            #pragma unroll
            for (int jr = 0; jr < 4; ++jr) {
                const int r = ty + 16 * jr;
                #pragma unroll
                for (int jc = 0; jc < 4; ++jc) {
                    const int c = tx + 16 * jc;
                    kp_w[r * 64 + ((((c >> 2) ^ (r & 15)) << 2) | (c & 3))] = s[jr][jc];
                }
            }
        }
        __syncthreads();

        // ---- O += P V  (thread tile rows r=ty+16jr, output dims dd=4tx..4tx+3) ----
        #pragma unroll 4
        for (int c4 = 0; c4 < 16; ++c4) {
            float4 a[4];
            #pragma unroll
            for (int jr = 0; jr < 4; ++jr) {
                const int r = ty + 16 * jr;
                a[jr] = kp_sm[r * 16 + (c4 ^ (r & 15))];   // P[r][4c4..4c4+3], broadcast
            }
            #pragma unroll
            for (int cc = 0; cc < 4; ++cc) {
                const int c = c4 * 4 + cc;
                const float4 b = v_sm[c * 16 + (tx ^ (c & 15))];   // V[c][4tx..4tx+3]
                #pragma unroll
                for (int jr = 0; jr < 4; ++jr) {
                    const float pa = (cc == 0) ? a[jr].x
                                   : (cc == 1) ? a[jr].y
                                   : (cc == 2) ? a[jr].z
                                               : a[jr].w;
                    o[jr][0] += pa * b.x;
                    o[jr][1] += pa * b.y;
                    o[jr][2] += pa * b.z;
                    o[jr][3] += pa * b.w;
                }
            }
        }
    }

    // ---- epilogue: normalize and store (coalesced float4) ----
    #pragma unroll
    for (int jr = 0; jr < 4; ++jr) {
        const float inv = 1.0f / l_run[jr];
        float4 ov;
        ov.x = o[jr][0] * inv;
        ov.y = o[jr][1] * inv;
        ov.z = o[jr][2] * inv;
        ov.w = o[jr][3] * inv;
        *reinterpret_cast<float4*>(
            O + (size_t)(h * Sn + q0 + ty + 16 * jr) * Dn + tx * 4) = ov;
    }
}

extern "C" void kernel_launch(void* const* d_in, const int* in_sizes, int n_in,
                              void* d_out, int out_size)
{
    (void)in_sizes; (void)n_in; (void)out_size;
    const float* Qp = (const float*)d_in[0];
    const float* Kp = (const float*)d_in[1];
    const float* Vp = (const float*)d_in[2];
    const float* Mp = (const float*)d_in[3];
    float* Op = (float*)d_out;

    dim3 grid(Sn / BQ, Hn);
    sdpa_fp32_kernel<<<grid, 256>>>(Qp, Kp, Vp, Mp, Op);
}